// round 15
// baseline (speedup 1.0000x reference)
#include <cuda_runtime.h>
#include <cuda_fp16.h>
#include <cstdint>

#define BB   128
#define TT   256
#define NN   100
#define SS   7
#define GG   16
#define FF   35
#define GROW 64   // gi row length in halfs (48 used, padded+swizzled to 128B)
#define H1ROW 520 // H1T row stride (floats): 512 + 8 pad

typedef unsigned long long ull;

// gi scratch: [n][t][b][GROW] fp16, rows swizzled by s(b) = ((b>>3)&7)*4 (half2 words)
__device__ __half g_gi[(size_t)NN * TT * BB * GROW];

__device__ __forceinline__ ull fma2(ull a, ull b, ull c) {
    ull d; asm("fma.rn.f32x2 %0, %1, %2, %3;" : "=l"(d) : "l"(a), "l"(b), "l"(c));
    return d;
}
__device__ __forceinline__ ull dup2(float w) {
    ull d; asm("mov.b64 %0, {%1, %1};" : "=l"(d) : "f"(w));
    return d;
}
__device__ __forceinline__ float plo(ull p) { return __int_as_float((int)(unsigned)p); }
__device__ __forceinline__ float phi(ull p) { return __int_as_float((int)(p >> 32)); }

__device__ __forceinline__ float tanhhw(float x) {
    float y; asm("tanh.approx.f32 %0, %1;" : "=f"(y) : "f"(x));
    return y;
}
__device__ __forceinline__ float sighw(float x) {
    return 0.5f * tanhhw(0.5f * x) + 0.5f;
}

__device__ __forceinline__ void cpasync4(uint32_t saddr, const float* gptr, int vbytes) {
    asm volatile("cp.async.ca.shared.global [%0], [%1], 4, %2;"
                 :: "r"(saddr), "l"(gptr), "r"(vbytes));
}
__device__ __forceinline__ void cpcommit() {
    asm volatile("cp.async.commit_group;");
}
__device__ __forceinline__ void cpwait0() {
    asm volatile("cp.async.wait_group 0;");
}

// ============================================================================
// Kernel A: gi GEMM -> g_gi[n][t][b][GROW] fp16.
// Weights pre-DUPLICATED in smem (wdd, ull pairs) so the inner loop has ZERO
// MOVs: per f = 4 LDS.64 (x pairs) + 6 LDS.64 (w dup) + 24 fma2.
// acc[jj 0..5][bp 0..3]: gate j=jq*6+jj, batches (bq*8+2bp, +1).
// Warp-local transpose handoff (warp w owns osm rows 32w..32w+31).
// Also zeroes out[] (block x==0) so the fused BC kernel can atomicAdd.
// ============================================================================
#define ACH 16
#define XROW 132   // padded xs row (floats), 16B-aligned stride

__global__ void __launch_bounds__(128) gi_gemm_kernel(
    const float* __restrict__ x,
    const float* __restrict__ Wih,
    float* __restrict__ out)
{
    extern __shared__ __align__(16) float smraw[];
    ull*     wdd = reinterpret_cast<ull*>(smraw);       // [35][48] dup'd pairs
    float*   xs  = smraw + 35 * 48 * 2;                 // [2][35][XROW]
    __half2* osm = reinterpret_cast<__half2*>(xs + 2 * 35 * XROW); // [128][32]

    const int n    = blockIdx.y;
    const int t0   = blockIdx.x * ACH;
    const int tid  = threadIdx.x;
    const int w    = tid >> 5;
    const int lane = tid & 31;
    const int jq   = tid & 7;      // owns gates j = jq*6 .. jq*6+5
    const int bq   = tid >> 3;     // owns batches b = bq*8 .. bq*8+7
    const int swz  = (bq & 7) * 4;

    if (blockIdx.x == 0) out[n * BB + tid] = 0.0f;

    // stage weights once, duplicated: wdd[f*48 + g] = dup2(Wih[n][g][f])
    const float* Wg = Wih + (size_t)n * 48 * FF;
    for (int i = tid; i < 48 * FF; i += 128)
        wdd[(i % FF) * 48 + (i / FF)] = dup2(Wg[i]);

    const int offs[5] = {0, -10, 1, 10, -1};
    const int s  = tid % 7;
    const int q  = tid / 7;
    const bool active = (q < 16);
    int nofs[5]; int vbytes[5];
    #pragma unroll
    for (int o = 0; o < 5; o++) {
        int n2 = n + offs[o];
        bool v = (n2 >= 0) && (n2 < NN);
        nofs[o]   = (v ? n2 : 0) * SS + s;
        vbytes[o] = v ? 4 : 0;
    }
    uint32_t xs_base = (uint32_t)__cvta_generic_to_shared(xs);

    auto stage = [&](int buf, int t) {
        if (active) {
            #pragma unroll
            for (int o = 0; o < 5; o++) {
                int f = o * 7 + s;
                #pragma unroll
                for (int bc = 0; bc < 8; bc++) {
                    int b = bc * 16 + q;
                    const float* gp = x + (size_t)b * (TT * NN * SS)
                                        + (size_t)t * (NN * SS) + nofs[o];
                    uint32_t sa = xs_base + (uint32_t)((buf * 35 * XROW + f * XROW + b) * 4);
                    cpasync4(sa, gp, vbytes[o]);
                }
            }
        }
        cpcommit();
    };

    stage(0, t0);
    cpwait0();
    __syncthreads();

    for (int tt = 0; tt < ACH; tt++) {
        const int t   = t0 + tt;
        const int cur = tt & 1;

        if (tt < ACH - 1) stage(cur ^ 1, t + 1);

        const float* xc = xs + cur * 35 * XROW;
        ull acc[6][4];   // [jj][bp]
        #pragma unroll
        for (int jj = 0; jj < 6; jj++)
            #pragma unroll
            for (int bp = 0; bp < 4; bp++) acc[jj][bp] = 0ULL;

        #pragma unroll 5
        for (int f = 0; f < FF; f++) {
            const ull* xp = reinterpret_cast<const ull*>(&xc[f * XROW + bq * 8]);
            ull x0 = xp[0], x1 = xp[1], x2 = xp[2], x3 = xp[3];
            const ull* wp = wdd + f * 48 + jq * 6;
            #pragma unroll
            for (int jj = 0; jj < 6; jj++) {
                ull wv = wp[jj];
                acc[jj][0] = fma2(x0, wv, acc[jj][0]);
                acc[jj][1] = fma2(x1, wv, acc[jj][1]);
                acc[jj][2] = fma2(x2, wv, acc[jj][2]);
                acc[jj][3] = fma2(x3, wv, acc[jj][3]);
            }
        }

        // swizzled STS: rows (bq*8+2bp, +1); word (jq*3+i)^swz holds gates
        // (jq*6+2i, jq*6+2i+1) — lo halves -> even row, hi halves -> odd row.
        #pragma unroll
        for (int bp = 0; bp < 4; bp++) {
            __half2* row0 = osm + (size_t)(bq * 8 + 2 * bp) * 32;
            __half2* row1 = row0 + 32;
            row0[(jq * 3 + 0) ^ swz] = __floats2half2_rn(plo(acc[0][bp]), plo(acc[1][bp]));
            row0[(jq * 3 + 1) ^ swz] = __floats2half2_rn(plo(acc[2][bp]), plo(acc[3][bp]));
            row0[(jq * 3 + 2) ^ swz] = __floats2half2_rn(plo(acc[4][bp]), plo(acc[5][bp]));
            row1[(jq * 3 + 0) ^ swz] = __floats2half2_rn(phi(acc[0][bp]), phi(acc[1][bp]));
            row1[(jq * 3 + 1) ^ swz] = __floats2half2_rn(phi(acc[2][bp]), phi(acc[3][bp]));
            row1[(jq * 3 + 2) ^ swz] = __floats2half2_rn(phi(acc[4][bp]), phi(acc[5][bp]));
        }
        __syncwarp();

        // warp-local coalesced copy-out of OWN rows 32w..32w+31
        {
            const float4* src = reinterpret_cast<const float4*>(osm);
            float4* dst = reinterpret_cast<float4*>(
                g_gi + (size_t)(n * TT + t) * BB * GROW);
            #pragma unroll
            for (int r = 0; r < 8; r++) {
                int idx = w * 256 + r * 32 + lane;
                dst[idx] = src[idx];
            }
        }

        cpwait0();
        __syncthreads();   // xs[cur] reads done block-wide; staged buf visible
    }
}

// ============================================================================
// Fused BC: 1600 blocks x 256 threads, role = bid & 1 (round-9 verbatim).
//   role B (even, 800): lm MLP for 16 batches.
//   role C (odd, 800): GRU recurrence, 8-deep chains, tanh.approx gates.
// ============================================================================
__global__ void __launch_bounds__(256) bc_fused_kernel(
    const float* __restrict__ x,
    const float* __restrict__ W1, const float* __restrict__ b1,
    const float* __restrict__ W2, const float* __restrict__ b2,
    const float* __restrict__ W3, const float* __restrict__ b3,
    const float* __restrict__ Whh,
    const float* __restrict__ bih, const float* __restrict__ bhh,
    const float* __restrict__ scW1, const float* __restrict__ scb1,
    const float* __restrict__ scW2, const float* __restrict__ scb2,
    const float* __restrict__ scW3, const float* __restrict__ scb3,
    float* __restrict__ out)
{
    extern __shared__ __align__(16) float dyn[];   // B: H1T[16][H1ROW]; C: shf
    __shared__ __align__(16) float xlsT[FF][16];
    __shared__ __align__(16) float part[16][65];
    __shared__ float sp2[16][17];

    const int bid = blockIdx.x;
    const int tid = threadIdx.x;

    if ((bid & 1) == 0) {
        // ==================== role B: lm MLP (16 batches) ====================
        const int bidx = bid >> 1;         // 0..799
        const int n    = bidx >> 3;
        const int bh16 = (bidx & 7) * 16;
        float* H1T = dyn;                  // [16][H1ROW]
        const int offs[5] = {0, -10, 1, 10, -1};

        for (int idx = tid; idx < FF * 16; idx += 256) {
            int f = idx >> 4, b = idx & 15;
            int o = f / SS, sx = f % SS;
            int n2 = n + offs[o];
            float v = 0.0f;
            if (n2 >= 0 && n2 < NN) {
                size_t gb = (size_t)(bh16 + b);
                v = x[(gb * TT + (TT - 1)) * (NN * SS) + n2 * SS + sx];
            }
            xlsT[f][b] = v;
        }
        __syncthreads();

        // layer 1: 512h x 16b
        {
            const float* W1g = W1 + (size_t)n * FF * 512;
            const float* b1g = b1 + (size_t)n * 512;
            const int hg = tid & 63;
            const int bg = tid >> 6;
            ull acc[4][4];
            #pragma unroll
            for (int b = 0; b < 4; b++)
                #pragma unroll
                for (int hp = 0; hp < 4; hp++) acc[b][hp] = 0ULL;

            #pragma unroll 5
            for (int f = 0; f < FF; f++) {
                float4 xv = *reinterpret_cast<const float4*>(&xlsT[f][bg * 4]);
                ull xd[4] = {dup2(xv.x), dup2(xv.y), dup2(xv.z), dup2(xv.w)};
                const ull* wp = reinterpret_cast<const ull*>(W1g + f * 512 + hg * 8);
                ull w0 = wp[0], w1 = wp[1], w2 = wp[2], w3 = wp[3];
                #pragma unroll
                for (int b = 0; b < 4; b++) {
                    acc[b][0] = fma2(xd[b], w0, acc[b][0]);
                    acc[b][1] = fma2(xd[b], w1, acc[b][1]);
                    acc[b][2] = fma2(xd[b], w2, acc[b][2]);
                    acc[b][3] = fma2(xd[b], w3, acc[b][3]);
                }
            }
            const float4* bp = reinterpret_cast<const float4*>(b1g + hg * 8);
            float4 ba = bp[0], bb = bp[1];
            float bias[8] = {ba.x, ba.y, ba.z, ba.w, bb.x, bb.y, bb.z, bb.w};
            #pragma unroll
            for (int b = 0; b < 4; b++) {
                float v[8];
                #pragma unroll
                for (int hp = 0; hp < 4; hp++) {
                    v[2*hp]   = fmaxf(plo(acc[b][hp]) + bias[2*hp],   0.0f);
                    v[2*hp+1] = fmaxf(phi(acc[b][hp]) + bias[2*hp+1], 0.0f);
                }
                float* row = &H1T[(size_t)(bg * 4 + b) * H1ROW + hg * 8];
                reinterpret_cast<float4*>(row)[0] = make_float4(v[0], v[1], v[2], v[3]);
                reinterpret_cast<float4*>(row)[1] = make_float4(v[4], v[5], v[6], v[7]);
            }
        }
        __syncthreads();

        // layer 2 + 3 folded
        {
            const float* W2g = W2 + (size_t)n * 512 * 256;
            const int hg = tid & 63;
            const int bg = tid >> 6;
            ull acc2[4][2];
            #pragma unroll
            for (int b = 0; b < 4; b++) { acc2[b][0] = 0ULL; acc2[b][1] = 0ULL; }

            #pragma unroll 2
            for (int f4 = 0; f4 < 128; f4++) {
                ull w[4][2];
                #pragma unroll
                for (int ff = 0; ff < 4; ff++) {
                    const ull* wp = reinterpret_cast<const ull*>(
                        W2g + (size_t)(f4 * 4 + ff) * 256 + hg * 4);
                    w[ff][0] = wp[0]; w[ff][1] = wp[1];
                }
                float4 h1v[4];
                #pragma unroll
                for (int b = 0; b < 4; b++)
                    h1v[b] = *reinterpret_cast<const float4*>(
                        &H1T[(size_t)(bg * 4 + b) * H1ROW + f4 * 4]);
                #pragma unroll
                for (int ff = 0; ff < 4; ff++) {
                    #pragma unroll
                    for (int b = 0; b < 4; b++) {
                        float hv = reinterpret_cast<const float*>(&h1v[b])[ff];
                        ull xd = dup2(hv);
                        acc2[b][0] = fma2(xd, w[ff][0], acc2[b][0]);
                        acc2[b][1] = fma2(xd, w[ff][1], acc2[b][1]);
                    }
                }
            }

            float4 b2v = *reinterpret_cast<const float4*>(b2 + (size_t)n * 256 + hg * 4);
            float4 w3v = *reinterpret_cast<const float4*>(W3 + (size_t)n * 256 + hg * 4);
            #pragma unroll
            for (int b = 0; b < 4; b++) {
                float v0 = fmaxf(plo(acc2[b][0]) + b2v.x, 0.0f);
                float v1 = fmaxf(phi(acc2[b][0]) + b2v.y, 0.0f);
                float v2 = fmaxf(plo(acc2[b][1]) + b2v.z, 0.0f);
                float v3 = fmaxf(phi(acc2[b][1]) + b2v.w, 0.0f);
                part[bg * 4 + b][hg] = v0 * w3v.x + v1 * w3v.y + v2 * w3v.z + v3 * w3v.w;
            }
        }
        __syncthreads();

        {
            int rb = tid >> 4, seg = tid & 15;
            float s = part[rb][seg * 4 + 0] + part[rb][seg * 4 + 1]
                    + part[rb][seg * 4 + 2] + part[rb][seg * 4 + 3];
            sp2[rb][seg] = s;
        }
        __syncthreads();
        if (tid < 16) {
            float tot = b3[n];
            #pragma unroll
            for (int seg = 0; seg < 16; seg++) tot += sp2[tid][seg];
            atomicAdd(&out[n * BB + bh16 + tid], tot);
        }
    } else {
        // ==================== role C: GRU recurrence ====================
        const int cidx  = bid >> 1;        // 0..799
        const int n     = cidx >> 3;
        const int bbase = (cidx & 7) * 16;

        float (*shf)[2][2][16] = reinterpret_cast<float(*)[2][2][16]>(dyn); // [8 warps]

        const int w    = tid >> 5;
        const int lane = tid & 31;
        const int j    = lane & 15;
        const int bh   = lane >> 4;
        const int bglob = bbase + w * 2 + bh;

        const ull* wrp = reinterpret_cast<const ull*>(Whh + ((size_t)n * 48 + j     ) * GG);
        const ull* wzp = reinterpret_cast<const ull*>(Whh + ((size_t)n * 48 + j + 16) * GG);
        const ull* wnp = reinterpret_cast<const ull*>(Whh + ((size_t)n * 48 + j + 32) * GG);
        ull wr[8], wz[8], wn[8];
        #pragma unroll
        for (int k = 0; k < 8; k++) { wr[k] = wrp[k]; wz[k] = wzp[k]; wn[k] = wnp[k]; }

        const float br  = bih[n * 48 + j     ] + bhh[n * 48 + j     ];
        const float bz  = bih[n * 48 + j + 16] + bhh[n * 48 + j + 16];
        const float bin = bih[n * 48 + j + 32];
        const float bhn = bhh[n * 48 + j + 32];

        const int sw  = ((bglob >> 3) & 7) * 4;
        const int o_r = (((j      ) >> 1) ^ sw) * 2 + (j & 1);
        const int o_z = (((j + 16 ) >> 1) ^ sw) * 2 + (j & 1);
        const int o_n = (((j + 32 ) >> 1) ^ sw) * 2 + (j & 1);

        shf[w][0][bh][j] = 0.0f;
        float hreg = 0.0f;
        __syncwarp();

        const __half* gbase = g_gi + ((size_t)n * TT * BB + bglob) * GROW;
        float gir = __half2float(gbase[o_r]);
        float giz = __half2float(gbase[o_z]);
        float gin = __half2float(gbase[o_n]);

        int cur = 0;
        for (int t = 0; t < TT; t++) {
            const __half* grn = gbase + (size_t)((t + 1 < TT) ? t + 1 : t) * BB * GROW;
            float pgr = __half2float(grn[o_r]);
            float pgz = __half2float(grn[o_z]);
            float pgn = __half2float(grn[o_n]);

            const ull* hp = reinterpret_cast<const ull*>(&shf[w][cur][bh][0]);
            ull ar = 0ULL, az = 0ULL, an = 0ULL;
            #pragma unroll
            for (int k = 0; k < 8; k++) {
                ull hk = hp[k];
                ar = fma2(hk, wr[k], ar);
                az = fma2(hk, wz[k], az);
                an = fma2(hk, wn[k], an);
            }
            float r  = sighw(br + gir + plo(ar) + phi(ar));
            float z  = sighw(bz + giz + plo(az) + phi(az));
            float nv = tanhhw(bin + gin + r * (bhn + plo(an) + phi(an)));
            float hnew = nv + z * (hreg - nv);
            hreg = hnew;
            shf[w][cur ^ 1][bh][j] = hnew;
            __syncwarp();
            gir = pgr; giz = pgz; gin = pgn;
            cur ^= 1;
        }

        // sc MLP epilogue
        shf[w][0][bh][j] = hreg;
        __syncwarp();
        {
            float a = scb1[n * GG + j];
            #pragma unroll
            for (int k = 0; k < GG; k++)
                a = fmaf(shf[w][0][bh][k], scW1[((size_t)n * GG + k) * GG + j], a);
            shf[w][1][bh][j] = fmaxf(a, 0.0f);
        }
        __syncwarp();
        {
            float a = scb2[n * GG + j];
            #pragma unroll
            for (int k = 0; k < GG; k++)
                a = fmaf(shf[w][1][bh][k], scW2[((size_t)n * GG + k) * GG + j], a);
            shf[w][0][bh][j] = fmaxf(a, 0.0f);
        }
        __syncwarp();
        if (j == 0) {
            float q = scb3[n];
            #pragma unroll
            for (int k = 0; k < GG; k++)
                q = fmaf(shf[w][0][bh][k], scW3[n * GG + k], q);
            atomicAdd(&out[n * BB + bglob], q);
        }
    }
}

// ============================================================================
extern "C" void kernel_launch(void* const* d_in, const int* in_sizes, int n_in,
                              void* d_out, int out_size) {
    const float* x      = (const float*)d_in[0];
    const float* lm_W1  = (const float*)d_in[1];
    const float* lm_b1  = (const float*)d_in[2];
    const float* lm_W2  = (const float*)d_in[3];
    const float* lm_b2  = (const float*)d_in[4];
    const float* lm_W3  = (const float*)d_in[5];
    const float* lm_b3  = (const float*)d_in[6];
    const float* gWih   = (const float*)d_in[7];
    const float* gWhh   = (const float*)d_in[8];
    const float* gbih   = (const float*)d_in[9];
    const float* gbhh   = (const float*)d_in[10];
    const float* scW1   = (const float*)d_in[11];
    const float* scb1   = (const float*)d_in[12];
    const float* scW2   = (const float*)d_in[13];
    const float* scb2   = (const float*)d_in[14];
    const float* scW3   = (const float*)d_in[15];
    const float* scb3   = (const float*)d_in[16];
    float* out = (float*)d_out;

    const int bc_bytes = 16 * H1ROW * 4;                                   // 33280
    const int a_bytes  = 35*48*8 + (2*35*XROW) * 4 + 128 * 32 * 4;         // 66784
    cudaFuncSetAttribute(bc_fused_kernel,
                         cudaFuncAttributeMaxDynamicSharedMemorySize, bc_bytes);
    cudaFuncSetAttribute(gi_gemm_kernel,
                         cudaFuncAttributeMaxDynamicSharedMemorySize, a_bytes);

    // A: gi GEMM (+ zero out)
    dim3 gridA(TT / ACH, NN), blockA(128);
    gi_gemm_kernel<<<gridA, blockA, a_bytes>>>(x, gWih, out);

    // BC fused: lm MLP + GRU recurrence, co-scheduled
    bc_fused_kernel<<<1600, 256, bc_bytes>>>(
        x, lm_W1, lm_b1, lm_W2, lm_b2, lm_W3, lm_b3,
        gWhh, gbih, gbhh,
        scW1, scb1, scW2, scb2, scW3, scb3, out);
}

// round 16
// speedup vs baseline: 1.3157x; 1.3157x over previous
#include <cuda_runtime.h>
#include <cuda_fp16.h>
#include <cstdint>

#define BB   128
#define TT   256
#define NN   100
#define SS   7
#define GG   16
#define FF   35
#define GROW 64   // gi row length in halfs (48 used, padded+swizzled to 128B)
#define H1ROW 520 // H1T row stride (floats): 512 + 8 pad

typedef unsigned long long ull;

// gi scratch: [n][t][b][GROW] fp16, rows swizzled by s(b) = ((b>>3)&7)*4 (half2 words)
__device__ __half g_gi[(size_t)NN * TT * BB * GROW];

__device__ __forceinline__ ull fma2(ull a, ull b, ull c) {
    ull d; asm("fma.rn.f32x2 %0, %1, %2, %3;" : "=l"(d) : "l"(a), "l"(b), "l"(c));
    return d;
}
__device__ __forceinline__ ull dup2(float w) {
    ull d; asm("mov.b64 %0, {%1, %1};" : "=l"(d) : "f"(w));
    return d;
}
__device__ __forceinline__ float plo(ull p) { return __int_as_float((int)(unsigned)p); }
__device__ __forceinline__ float phi(ull p) { return __int_as_float((int)(p >> 32)); }

__device__ __forceinline__ float tanhhw(float x) {
    float y; asm("tanh.approx.f32 %0, %1;" : "=f"(y) : "f"(x));
    return y;
}
__device__ __forceinline__ float sighw(float x) {
    return 0.5f * tanhhw(0.5f * x) + 0.5f;
}

__device__ __forceinline__ void cpasync4(uint32_t saddr, const float* gptr, int vbytes) {
    asm volatile("cp.async.ca.shared.global [%0], [%1], 4, %2;"
                 :: "r"(saddr), "l"(gptr), "r"(vbytes));
}
__device__ __forceinline__ void cpcommit() {
    asm volatile("cp.async.commit_group;");
}
__device__ __forceinline__ void cpwait0() {
    asm volatile("cp.async.wait_group 0;");
}

// ============================================================================
// Kernel A (round-14 proven version): gi GEMM -> g_gi[n][t][b][GROW] fp16.
// Warp-local transpose handoff; one block sync per timestep.
// Also zeroes out[] (block x==0) so the fused BC kernel can atomicAdd.
// ============================================================================
#define ACH 16
#define XROW 132   // padded xs row (floats), 16B-aligned stride

__global__ void __launch_bounds__(128) gi_gemm_kernel(
    const float* __restrict__ x,
    const float* __restrict__ Wih,
    float* __restrict__ out)
{
    extern __shared__ __align__(16) float smraw[];
    float*   wd  = smraw;                    // [35][48], j consecutive
    float*   xs  = wd + 35 * 48;             // [2][35][XROW]
    __half2* osm = reinterpret_cast<__half2*>(xs + 2 * 35 * XROW); // [128][32]

    const int n    = blockIdx.y;
    const int t0   = blockIdx.x * ACH;
    const int tid  = threadIdx.x;
    const int w    = tid >> 5;
    const int lane = tid & 31;
    const int jq   = tid & 7;      // owns j = jq*6 .. jq*6+5
    const int bq   = tid >> 3;     // owns b = bq*8 .. bq*8+7
    const int swz  = (bq & 7) * 4;

    if (blockIdx.x == 0) out[n * BB + tid] = 0.0f;

    const float* Wg = Wih + (size_t)n * 48 * FF;
    for (int i = tid; i < 48 * FF; i += 128)
        wd[(i % FF) * 48 + (i / FF)] = Wg[i];

    const int offs[5] = {0, -10, 1, 10, -1};
    const int s  = tid % 7;
    const int q  = tid / 7;
    const bool active = (q < 16);
    int nofs[5]; int vbytes[5];
    #pragma unroll
    for (int o = 0; o < 5; o++) {
        int n2 = n + offs[o];
        bool v = (n2 >= 0) && (n2 < NN);
        nofs[o]   = (v ? n2 : 0) * SS + s;
        vbytes[o] = v ? 4 : 0;
    }
    uint32_t xs_base = (uint32_t)__cvta_generic_to_shared(xs);

    auto stage = [&](int buf, int t) {
        if (active) {
            #pragma unroll
            for (int o = 0; o < 5; o++) {
                int f = o * 7 + s;
                #pragma unroll
                for (int bc = 0; bc < 8; bc++) {
                    int b = bc * 16 + q;
                    const float* gp = x + (size_t)b * (TT * NN * SS)
                                        + (size_t)t * (NN * SS) + nofs[o];
                    uint32_t sa = xs_base + (uint32_t)((buf * 35 * XROW + f * XROW + b) * 4);
                    cpasync4(sa, gp, vbytes[o]);
                }
            }
        }
        cpcommit();
    };

    stage(0, t0);
    cpwait0();
    __syncthreads();

    for (int tt = 0; tt < ACH; tt++) {
        const int t   = t0 + tt;
        const int cur = tt & 1;

        if (tt < ACH - 1) stage(cur ^ 1, t + 1);

        const float* xc = xs + cur * 35 * XROW;
        ull acc[3][8];
        #pragma unroll
        for (int jp = 0; jp < 3; jp++)
            #pragma unroll
            for (int b = 0; b < 8; b++) acc[jp][b] = 0ULL;

        #pragma unroll 5
        for (int f = 0; f < FF; f++) {
            const float4* xp = reinterpret_cast<const float4*>(&xc[f * XROW + bq * 8]);
            float4 xa = xp[0], xb = xp[1];
            ull xd[8] = {dup2(xa.x), dup2(xa.y), dup2(xa.z), dup2(xa.w),
                         dup2(xb.x), dup2(xb.y), dup2(xb.z), dup2(xb.w)};
            const ull* wp = reinterpret_cast<const ull*>(&wd[f * 48 + jq * 6]);
            ull w0 = wp[0], w1 = wp[1], w2 = wp[2];
            #pragma unroll
            for (int b = 0; b < 8; b++) {
                acc[0][b] = fma2(xd[b], w0, acc[0][b]);
                acc[1][b] = fma2(xd[b], w1, acc[1][b]);
                acc[2][b] = fma2(xd[b], w2, acc[2][b]);
            }
        }

        // swizzled STS: row b (32 half2), word (jq*3+i) ^ swz — conflict-free.
        #pragma unroll
        for (int ib = 0; ib < 8; ib++) {
            __half2* row = osm + (size_t)(bq * 8 + ib) * 32;
            row[(jq * 3 + 0) ^ swz] = __floats2half2_rn(plo(acc[0][ib]), phi(acc[0][ib]));
            row[(jq * 3 + 1) ^ swz] = __floats2half2_rn(plo(acc[1][ib]), phi(acc[1][ib]));
            row[(jq * 3 + 2) ^ swz] = __floats2half2_rn(plo(acc[2][ib]), phi(acc[2][ib]));
        }
        __syncwarp();

        // warp-local coalesced copy-out of OWN rows 32w..32w+31
        {
            const float4* src = reinterpret_cast<const float4*>(osm);
            float4* dst = reinterpret_cast<float4*>(
                g_gi + (size_t)(n * TT + t) * BB * GROW);
            #pragma unroll
            for (int r = 0; r < 8; r++) {
                int idx = w * 256 + r * 32 + lane;
                dst[idx] = src[idx];
            }
        }

        cpwait0();
        __syncthreads();   // xs[cur] reads done block-wide; staged buf visible
    }
}

// ============================================================================
// Fused BC: 3200 blocks x 128 threads, role = bid & 1, 8 batches per block.
// 5 blocks/SM by registers (12.3K/block) -> occ ~31%.
//   role B (even, 1600): lm MLP for 8 batches.
//   role C (odd, 1600): GRU recurrence (4 warps x 2 batches, warp-local).
// ============================================================================
__global__ void __launch_bounds__(128) bc_fused_kernel(
    const float* __restrict__ x,
    const float* __restrict__ W1, const float* __restrict__ b1,
    const float* __restrict__ W2, const float* __restrict__ b2,
    const float* __restrict__ W3, const float* __restrict__ b3,
    const float* __restrict__ Whh,
    const float* __restrict__ bih, const float* __restrict__ bhh,
    const float* __restrict__ scW1, const float* __restrict__ scb1,
    const float* __restrict__ scW2, const float* __restrict__ scb2,
    const float* __restrict__ scW3, const float* __restrict__ scb3,
    float* __restrict__ out)
{
    extern __shared__ __align__(16) float dyn[];   // B: H1T[8][H1ROW]; C: shf
    __shared__ __align__(16) float xlsT[FF][8];
    __shared__ __align__(16) float part[8][65];
    __shared__ float sp2[8][17];

    const int bid = blockIdx.x;
    const int tid = threadIdx.x;

    if ((bid & 1) == 0) {
        // ==================== role B: lm MLP (8 batches) ====================
        const int bidx = bid >> 1;          // 0..1599
        const int n    = bidx >> 4;
        const int bh8  = (bidx & 15) * 8;
        float* H1T = dyn;                   // [8][H1ROW]
        const int offs[5] = {0, -10, 1, 10, -1};

        for (int idx = tid; idx < FF * 8; idx += 128) {
            int f = idx >> 3, b = idx & 7;
            int o = f / SS, sx = f % SS;
            int n2 = n + offs[o];
            float v = 0.0f;
            if (n2 >= 0 && n2 < NN) {
                size_t gb = (size_t)(bh8 + b);
                v = x[(gb * TT + (TT - 1)) * (NN * SS) + n2 * SS + sx];
            }
            xlsT[f][b] = v;
        }
        __syncthreads();

        // layer 1: 512h x 8b. Thread: hg=tid&63 (8 h), bg=tid>>6 (4 b).
        {
            const float* W1g = W1 + (size_t)n * FF * 512;
            const float* b1g = b1 + (size_t)n * 512;
            const int hg = tid & 63;
            const int bg = tid >> 6;    // 0..1
            ull acc[4][4];
            #pragma unroll
            for (int b = 0; b < 4; b++)
                #pragma unroll
                for (int hp = 0; hp < 4; hp++) acc[b][hp] = 0ULL;

            #pragma unroll 5
            for (int f = 0; f < FF; f++) {
                float4 xv = *reinterpret_cast<const float4*>(&xlsT[f][bg * 4]);
                ull xd[4] = {dup2(xv.x), dup2(xv.y), dup2(xv.z), dup2(xv.w)};
                const ull* wp = reinterpret_cast<const ull*>(W1g + f * 512 + hg * 8);
                ull w0 = wp[0], w1 = wp[1], w2 = wp[2], w3 = wp[3];
                #pragma unroll
                for (int b = 0; b < 4; b++) {
                    acc[b][0] = fma2(xd[b], w0, acc[b][0]);
                    acc[b][1] = fma2(xd[b], w1, acc[b][1]);
                    acc[b][2] = fma2(xd[b], w2, acc[b][2]);
                    acc[b][3] = fma2(xd[b], w3, acc[b][3]);
                }
            }
            const float4* bp = reinterpret_cast<const float4*>(b1g + hg * 8);
            float4 ba = bp[0], bb = bp[1];
            float bias[8] = {ba.x, ba.y, ba.z, ba.w, bb.x, bb.y, bb.z, bb.w};
            #pragma unroll
            for (int b = 0; b < 4; b++) {
                float v[8];
                #pragma unroll
                for (int hp = 0; hp < 4; hp++) {
                    v[2*hp]   = fmaxf(plo(acc[b][hp]) + bias[2*hp],   0.0f);
                    v[2*hp+1] = fmaxf(phi(acc[b][hp]) + bias[2*hp+1], 0.0f);
                }
                float* row = &H1T[(size_t)(bg * 4 + b) * H1ROW + hg * 8];
                reinterpret_cast<float4*>(row)[0] = make_float4(v[0], v[1], v[2], v[3]);
                reinterpret_cast<float4*>(row)[1] = make_float4(v[4], v[5], v[6], v[7]);
            }
        }
        __syncthreads();

        // layer 2 + 3 folded: hg=tid&63 (4 h), bg=tid>>6 (4 b)
        {
            const float* W2g = W2 + (size_t)n * 512 * 256;
            const int hg = tid & 63;
            const int bg = tid >> 6;
            ull acc2[4][2];
            #pragma unroll
            for (int b = 0; b < 4; b++) { acc2[b][0] = 0ULL; acc2[b][1] = 0ULL; }

            #pragma unroll 2
            for (int f4 = 0; f4 < 128; f4++) {
                ull w[4][2];
                #pragma unroll
                for (int ff = 0; ff < 4; ff++) {
                    const ull* wp = reinterpret_cast<const ull*>(
                        W2g + (size_t)(f4 * 4 + ff) * 256 + hg * 4);
                    w[ff][0] = wp[0]; w[ff][1] = wp[1];
                }
                float4 h1v[4];
                #pragma unroll
                for (int b = 0; b < 4; b++)
                    h1v[b] = *reinterpret_cast<const float4*>(
                        &H1T[(size_t)(bg * 4 + b) * H1ROW + f4 * 4]);
                #pragma unroll
                for (int ff = 0; ff < 4; ff++) {
                    #pragma unroll
                    for (int b = 0; b < 4; b++) {
                        float hv = reinterpret_cast<const float*>(&h1v[b])[ff];
                        ull xd = dup2(hv);
                        acc2[b][0] = fma2(xd, w[ff][0], acc2[b][0]);
                        acc2[b][1] = fma2(xd, w[ff][1], acc2[b][1]);
                    }
                }
            }

            float4 b2v = *reinterpret_cast<const float4*>(b2 + (size_t)n * 256 + hg * 4);
            float4 w3v = *reinterpret_cast<const float4*>(W3 + (size_t)n * 256 + hg * 4);
            #pragma unroll
            for (int b = 0; b < 4; b++) {
                float v0 = fmaxf(plo(acc2[b][0]) + b2v.x, 0.0f);
                float v1 = fmaxf(phi(acc2[b][0]) + b2v.y, 0.0f);
                float v2 = fmaxf(plo(acc2[b][1]) + b2v.z, 0.0f);
                float v3 = fmaxf(phi(acc2[b][1]) + b2v.w, 0.0f);
                part[bg * 4 + b][hg] = v0 * w3v.x + v1 * w3v.y + v2 * w3v.z + v3 * w3v.w;
            }
        }
        __syncthreads();

        {
            int rb = tid >> 4, seg = tid & 15;   // 8 rows x 16 segs = 128
            float s = part[rb][seg * 4 + 0] + part[rb][seg * 4 + 1]
                    + part[rb][seg * 4 + 2] + part[rb][seg * 4 + 3];
            sp2[rb][seg] = s;
        }
        __syncthreads();
        if (tid < 8) {
            float tot = b3[n];
            #pragma unroll
            for (int seg = 0; seg < 16; seg++) tot += sp2[tid][seg];
            atomicAdd(&out[n * BB + bh8 + tid], tot);
        }
    } else {
        // ==================== role C: GRU recurrence (8 batches) ====================
        const int cidx  = bid >> 1;        // 0..1599
        const int n     = cidx >> 4;
        const int bbase = (cidx & 15) * 8;

        float (*shf)[2][2][16] = reinterpret_cast<float(*)[2][2][16]>(dyn); // [4 warps]

        const int w    = tid >> 5;
        const int lane = tid & 31;
        const int j    = lane & 15;
        const int bh   = lane >> 4;
        const int bglob = bbase + w * 2 + bh;

        const ull* wrp = reinterpret_cast<const ull*>(Whh + ((size_t)n * 48 + j     ) * GG);
        const ull* wzp = reinterpret_cast<const ull*>(Whh + ((size_t)n * 48 + j + 16) * GG);
        const ull* wnp = reinterpret_cast<const ull*>(Whh + ((size_t)n * 48 + j + 32) * GG);
        ull wr[8], wz[8], wn[8];
        #pragma unroll
        for (int k = 0; k < 8; k++) { wr[k] = wrp[k]; wz[k] = wzp[k]; wn[k] = wnp[k]; }

        const float br  = bih[n * 48 + j     ] + bhh[n * 48 + j     ];
        const float bz  = bih[n * 48 + j + 16] + bhh[n * 48 + j + 16];
        const float bin = bih[n * 48 + j + 32];
        const float bhn = bhh[n * 48 + j + 32];

        const int sw  = ((bglob >> 3) & 7) * 4;
        const int o_r = (((j      ) >> 1) ^ sw) * 2 + (j & 1);
        const int o_z = (((j + 16 ) >> 1) ^ sw) * 2 + (j & 1);
        const int o_n = (((j + 32 ) >> 1) ^ sw) * 2 + (j & 1);

        shf[w][0][bh][j] = 0.0f;
        float hreg = 0.0f;
        __syncwarp();

        const __half* gbase = g_gi + ((size_t)n * TT * BB + bglob) * GROW;
        float gir = __half2float(gbase[o_r]);
        float giz = __half2float(gbase[o_z]);
        float gin = __half2float(gbase[o_n]);

        int cur = 0;
        for (int t = 0; t < TT; t++) {
            const __half* grn = gbase + (size_t)((t + 1 < TT) ? t + 1 : t) * BB * GROW;
            float pgr = __half2float(grn[o_r]);
            float pgz = __half2float(grn[o_z]);
            float pgn = __half2float(grn[o_n]);

            const ull* hp = reinterpret_cast<const ull*>(&shf[w][cur][bh][0]);
            ull ar = 0ULL, az = 0ULL, an = 0ULL;
            #pragma unroll
            for (int k = 0; k < 8; k++) {
                ull hk = hp[k];
                ar = fma2(hk, wr[k], ar);
                az = fma2(hk, wz[k], az);
                an = fma2(hk, wn[k], an);
            }
            float r  = sighw(br + gir + plo(ar) + phi(ar));
            float z  = sighw(bz + giz + plo(az) + phi(az));
            float nv = tanhhw(bin + gin + r * (bhn + plo(an) + phi(an)));
            float hnew = nv + z * (hreg - nv);
            hreg = hnew;
            shf[w][cur ^ 1][bh][j] = hnew;
            __syncwarp();
            gir = pgr; giz = pgz; gin = pgn;
            cur ^= 1;
        }

        // sc MLP epilogue
        shf[w][0][bh][j] = hreg;
        __syncwarp();
        {
            float a = scb1[n * GG + j];
            #pragma unroll
            for (int k = 0; k < GG; k++)
                a = fmaf(shf[w][0][bh][k], scW1[((size_t)n * GG + k) * GG + j], a);
            shf[w][1][bh][j] = fmaxf(a, 0.0f);
        }
        __syncwarp();
        {
            float a = scb2[n * GG + j];
            #pragma unroll
            for (int k = 0; k < GG; k++)
                a = fmaf(shf[w][1][bh][k], scW2[((size_t)n * GG + k) * GG + j], a);
            shf[w][0][bh][j] = fmaxf(a, 0.0f);
        }
        __syncwarp();
        if (j == 0) {
            float q = scb3[n];
            #pragma unroll
            for (int k = 0; k < GG; k++)
                q = fmaf(shf[w][0][bh][k], scW3[n * GG + k], q);
            atomicAdd(&out[n * BB + bglob], q);
        }
    }
}

// ============================================================================
extern "C" void kernel_launch(void* const* d_in, const int* in_sizes, int n_in,
                              void* d_out, int out_size) {
    const float* x      = (const float*)d_in[0];
    const float* lm_W1  = (const float*)d_in[1];
    const float* lm_b1  = (const float*)d_in[2];
    const float* lm_W2  = (const float*)d_in[3];
    const float* lm_b2  = (const float*)d_in[4];
    const float* lm_W3  = (const float*)d_in[5];
    const float* lm_b3  = (const float*)d_in[6];
    const float* gWih   = (const float*)d_in[7];
    const float* gWhh   = (const float*)d_in[8];
    const float* gbih   = (const float*)d_in[9];
    const float* gbhh   = (const float*)d_in[10];
    const float* scW1   = (const float*)d_in[11];
    const float* scb1   = (const float*)d_in[12];
    const float* scW2   = (const float*)d_in[13];
    const float* scb2   = (const float*)d_in[14];
    const float* scW3   = (const float*)d_in[15];
    const float* scb3   = (const float*)d_in[16];
    float* out = (float*)d_out;

    const int bc_bytes = 8 * H1ROW * 4;                              // 16640
    const int a_bytes  = (35*48 + 2*35*XROW) * 4 + 128 * 32 * 4;     // 60064
    cudaFuncSetAttribute(bc_fused_kernel,
                         cudaFuncAttributeMaxDynamicSharedMemorySize, bc_bytes);
    cudaFuncSetAttribute(gi_gemm_kernel,
                         cudaFuncAttributeMaxDynamicSharedMemorySize, a_bytes);

    // A: gi GEMM (+ zero out)
    dim3 gridA(TT / ACH, NN), blockA(128);
    gi_gemm_kernel<<<gridA, blockA, a_bytes>>>(x, gWih, out);

    // BC fused: lm MLP + GRU recurrence, 128-thr blocks for 5 blocks/SM
    bc_fused_kernel<<<3200, 128, bc_bytes>>>(
        x, lm_W1, lm_b1, lm_W2, lm_b2, lm_W3, lm_b3,
        gWhh, gbih, gbhh,
        scW1, scb1, scW2, scb2, scW3, scb3, out);
}